// round 1
// baseline (speedup 1.0000x reference)
#include <cuda_runtime.h>
#include <cuda_bf16.h>
#include <math.h>

// ---------------------------------------------------------------------------
// ResGCN15: N=50000 nodes, E=800000 edges, NFEAT=256, NHID=128, NCLASS=40
// Pipeline per launch:
//   1. CSR build (hist -> scan -> scatter), dst-grouped
//   2. z = x@W0 + b0 ; sup = x@W1 ; x1 = relu(agg(sup)+b1) + z
//   3. 13x: sup = h@Wmid[l]; h = relu(agg(sup)+bmid[l]) + h
//   4. running acc += x_l @ W15[(14-l)*128 : (15-l)*128]   (avoids concat)
//   5. out = log_softmax(agg40(acc) + b15)
// ---------------------------------------------------------------------------

#define MAX_N 50000
#define MAX_E 800000
#define NHID 128
#define NCLASS 40

__device__ __align__(16) int   g_deg[MAX_N];
__device__ __align__(16) int   g_offs[MAX_N + 1];
__device__ __align__(16) int   g_cursor[MAX_N];
__device__ __align__(16) int   g_csr_src[MAX_E];
__device__ __align__(16) float g_csr_w[MAX_E];
__device__ __align__(16) float g_z[(size_t)MAX_N * NHID];
__device__ __align__(16) float g_h[(size_t)MAX_N * NHID];
__device__ __align__(16) float g_sup[(size_t)MAX_N * NHID];
__device__ __align__(16) float g_acc[(size_t)MAX_N * NCLASS];

// ---------------------------------------------------------------------------
// CSR build
// ---------------------------------------------------------------------------
__global__ void zero_deg_kernel(int n) {
    int i = blockIdx.x * blockDim.x + threadIdx.x;
    if (i < n) g_deg[i] = 0;
}

__global__ void hist_kernel(const int* __restrict__ dst, int E) {
    int i = blockIdx.x * blockDim.x + threadIdx.x;
    if (i < E) atomicAdd(&g_deg[dst[i]], 1);
}

// single-block exclusive scan over n degrees -> g_offs[0..n], g_cursor[i]=start
__global__ void scan_kernel(int n) {
    __shared__ int sums[1024];
    const int t = threadIdx.x;                 // blockDim = 1024
    const int chunk = (n + 1023) >> 10;
    const int begin = t * chunk;
    const int end = min(begin + chunk, n);
    int s = 0;
    for (int i = begin; i < end; i++) s += g_deg[i];
    sums[t] = s;
    __syncthreads();
    // Hillis-Steele inclusive scan
    for (int d = 1; d < 1024; d <<= 1) {
        int v = (t >= d) ? sums[t - d] : 0;
        __syncthreads();
        sums[t] += v;
        __syncthreads();
    }
    int run = (t == 0) ? 0 : sums[t - 1];      // exclusive prefix of this chunk
    if (t == 0) g_offs[0] = 0;
    for (int i = begin; i < end; i++) {
        g_cursor[i] = run;
        run += g_deg[i];
        g_offs[i + 1] = run;
    }
}

__global__ void scatter_kernel(const int* __restrict__ src, const int* __restrict__ dst,
                               const float* __restrict__ w, int E) {
    int i = blockIdx.x * blockDim.x + threadIdx.x;
    if (i < E) {
        int d = dst[i];
        int pos = atomicAdd(&g_cursor[d], 1);
        g_csr_src[pos] = src[i];
        g_csr_w[pos] = w[i];
    }
}

// ---------------------------------------------------------------------------
// GEMM: C[M,128] = A[M,K] @ B[K,128] (+ bias). BM=64, BN=128, BK=16.
// 256 threads, each computes an 8x4 microtile.
// ---------------------------------------------------------------------------
__global__ void __launch_bounds__(256) gemm128_kernel(
    const float* __restrict__ A, const float* __restrict__ B,
    const float* __restrict__ bias, float* __restrict__ C, int M, int K)
{
    __shared__ float As[16][64];   // k-major: a-fragment reads are warp broadcasts
    __shared__ float Bs[16][128];
    const int t = threadIdx.x;
    const int tx = t & 31;         // cols tx*4 .. tx*4+3
    const int ty = t >> 5;         // rows ty*8 .. ty*8+7
    const int row0 = blockIdx.x * 64;

    float acc[8][4];
#pragma unroll
    for (int i = 0; i < 8; i++)
#pragma unroll
        for (int j = 0; j < 4; j++) acc[i][j] = 0.f;

    const int ar = t >> 2;            // 0..63
    const int ac = (t & 3) << 2;      // 0,4,8,12
    const int br = t >> 5;            // 0..7
    const int bc = (t & 31) << 2;

    for (int k0 = 0; k0 < K; k0 += 16) {
        float4 av = make_float4(0.f, 0.f, 0.f, 0.f);
        if (row0 + ar < M)
            av = *(const float4*)(A + (size_t)(row0 + ar) * K + k0 + ac);
        As[ac + 0][ar] = av.x; As[ac + 1][ar] = av.y;
        As[ac + 2][ar] = av.z; As[ac + 3][ar] = av.w;
        *(float4*)&Bs[br][bc]     = *(const float4*)(B + (size_t)(k0 + br) * 128 + bc);
        *(float4*)&Bs[br + 8][bc] = *(const float4*)(B + (size_t)(k0 + br + 8) * 128 + bc);
        __syncthreads();
#pragma unroll
        for (int k = 0; k < 16; k++) {
            float4 b = *(const float4*)&Bs[k][tx << 2];
            float a[8];
#pragma unroll
            for (int i = 0; i < 8; i++) a[i] = As[k][ty * 8 + i];
#pragma unroll
            for (int i = 0; i < 8; i++) {
                acc[i][0] = fmaf(a[i], b.x, acc[i][0]);
                acc[i][1] = fmaf(a[i], b.y, acc[i][1]);
                acc[i][2] = fmaf(a[i], b.z, acc[i][2]);
                acc[i][3] = fmaf(a[i], b.w, acc[i][3]);
            }
        }
        __syncthreads();
    }
    float4 bv = make_float4(0.f, 0.f, 0.f, 0.f);
    if (bias) bv = *(const float4*)(bias + (tx << 2));
#pragma unroll
    for (int i = 0; i < 8; i++) {
        int r = row0 + ty * 8 + i;
        if (r < M) {
            float4 o;
            o.x = acc[i][0] + bv.x; o.y = acc[i][1] + bv.y;
            o.z = acc[i][2] + bv.z; o.w = acc[i][3] + bv.w;
            *(float4*)(C + (size_t)r * 128 + (tx << 2)) = o;
        }
    }
}

// ---------------------------------------------------------------------------
// acc[M,40] (+)= A[M,128] @ Wp[128,40].  blockDim (40,8), 32 rows per block.
// ---------------------------------------------------------------------------
__global__ void __launch_bounds__(320) acc_gemm40_kernel(
    const float* __restrict__ A, const float* __restrict__ Wp,
    float* __restrict__ Cacc, int M, int zero_first)
{
    __shared__ float Ws[128 * 40];   // 20KB
    __shared__ float As[32][128];    // 16KB
    const int tx = threadIdx.x;      // 0..39 (output col)
    const int ty = threadIdx.y;      // 0..7
    const int tid = ty * 40 + tx;
    const int row0 = blockIdx.x * 32;

    for (int i = tid; i < 128 * 40; i += 320) Ws[i] = Wp[i];
    for (int i = tid; i < 32 * 128; i += 320) {
        int r = i >> 7, k = i & 127;
        As[r][k] = (row0 + r < M) ? A[(size_t)(row0 + r) * 128 + k] : 0.f;
    }
    __syncthreads();

    float a0 = 0.f, a1 = 0.f, a2 = 0.f, a3 = 0.f;
#pragma unroll 8
    for (int k = 0; k < 128; k++) {
        float w = Ws[k * 40 + tx];
        a0 = fmaf(As[ty][k],      w, a0);
        a1 = fmaf(As[ty + 8][k],  w, a1);
        a2 = fmaf(As[ty + 16][k], w, a2);
        a3 = fmaf(As[ty + 24][k], w, a3);
    }
    float vals[4] = {a0, a1, a2, a3};
#pragma unroll
    for (int j = 0; j < 4; j++) {
        int r = row0 + ty + 8 * j;
        if (r < M) {
            size_t idx = (size_t)r * 40 + tx;
            Cacc[idx] = (zero_first ? 0.f : Cacc[idx]) + vals[j];
        }
    }
}

// ---------------------------------------------------------------------------
// SpMM d=128: warp per node. out = relu(sum_e w*sup[src] + bias) + res.
// res may alias out (warp only touches its own row).
// ---------------------------------------------------------------------------
__global__ void __launch_bounds__(256) spmm_relu_res_kernel(
    const float* __restrict__ support, const float* __restrict__ bias,
    const float* __restrict__ res, float* __restrict__ out, int n)
{
    const int node = (blockIdx.x * blockDim.x + threadIdx.x) >> 5;
    if (node >= n) return;
    const int lane = threadIdx.x & 31;
    const int s = g_offs[node], e = g_offs[node + 1];
    const float4* sup4 = (const float4*)support;

    float4 acc = make_float4(0.f, 0.f, 0.f, 0.f);
    int i = s;
    for (; i + 1 < e; i += 2) {
        int s0 = g_csr_src[i], s1 = g_csr_src[i + 1];
        float w0 = g_csr_w[i],  w1 = g_csr_w[i + 1];
        float4 v0 = sup4[(size_t)s0 * 32 + lane];
        float4 v1 = sup4[(size_t)s1 * 32 + lane];
        acc.x = fmaf(w0, v0.x, acc.x); acc.y = fmaf(w0, v0.y, acc.y);
        acc.z = fmaf(w0, v0.z, acc.z); acc.w = fmaf(w0, v0.w, acc.w);
        acc.x = fmaf(w1, v1.x, acc.x); acc.y = fmaf(w1, v1.y, acc.y);
        acc.z = fmaf(w1, v1.z, acc.z); acc.w = fmaf(w1, v1.w, acc.w);
    }
    if (i < e) {
        int s0 = g_csr_src[i];
        float w0 = g_csr_w[i];
        float4 v0 = sup4[(size_t)s0 * 32 + lane];
        acc.x = fmaf(w0, v0.x, acc.x); acc.y = fmaf(w0, v0.y, acc.y);
        acc.z = fmaf(w0, v0.z, acc.z); acc.w = fmaf(w0, v0.w, acc.w);
    }
    float4 b = ((const float4*)bias)[lane];
    float4 r = ((const float4*)res)[(size_t)node * 32 + lane];
    float4 o;
    o.x = fmaxf(acc.x + b.x, 0.f) + r.x;
    o.y = fmaxf(acc.y + b.y, 0.f) + r.y;
    o.z = fmaxf(acc.z + b.z, 0.f) + r.z;
    o.w = fmaxf(acc.w + b.w, 0.f) + r.w;
    ((float4*)out)[(size_t)node * 32 + lane] = o;
}

// ---------------------------------------------------------------------------
// Final: agg40 over acc, +b15, log_softmax. Warp per node.
// lane holds col=lane; lanes 0..7 also hold col=32+lane.
// ---------------------------------------------------------------------------
__global__ void __launch_bounds__(256) spmm40_lsm_kernel(
    const float* __restrict__ accum, const float* __restrict__ b15,
    float* __restrict__ out, int n)
{
    const int node = (blockIdx.x * blockDim.x + threadIdx.x) >> 5;
    if (node >= n) return;
    const int lane = threadIdx.x & 31;
    const int s = g_offs[node], e = g_offs[node + 1];

    float a1 = 0.f, a2 = 0.f;
    for (int i = s; i < e; i++) {
        int src = g_csr_src[i];
        float w = g_csr_w[i];
        const float* row = accum + (size_t)src * 40;
        a1 = fmaf(w, row[lane], a1);
        if (lane < 8) a2 = fmaf(w, row[32 + lane], a2);
    }
    float v1 = a1 + b15[lane];
    float v2 = (lane < 8) ? (a2 + b15[32 + lane]) : -3.0e38f;

    float m = fmaxf(v1, v2);
#pragma unroll
    for (int o = 16; o > 0; o >>= 1) m = fmaxf(m, __shfl_xor_sync(0xffffffffu, m, o));
    float sum = expf(v1 - m) + ((lane < 8) ? expf(v2 - m) : 0.f);
#pragma unroll
    for (int o = 16; o > 0; o >>= 1) sum += __shfl_xor_sync(0xffffffffu, sum, o);
    float ls = m + logf(sum);

    out[(size_t)node * 40 + lane] = v1 - ls;
    if (lane < 8) out[(size_t)node * 40 + 32 + lane] = v2 - ls;
}

// ---------------------------------------------------------------------------
// Launch
// ---------------------------------------------------------------------------
extern "C" void kernel_launch(void* const* d_in, const int* in_sizes, int n_in,
                              void* d_out, int out_size)
{
    const float* x    = (const float*)d_in[0];
    const int*   esrc = (const int*)  d_in[1];
    const int*   edst = (const int*)  d_in[2];
    const float* ew   = (const float*)d_in[3];
    const float* W0   = (const float*)d_in[4];
    const float* b0   = (const float*)d_in[5];
    const float* W1   = (const float*)d_in[6];
    const float* b1   = (const float*)d_in[7];
    const float* Wmid = (const float*)d_in[8];
    const float* bmid = (const float*)d_in[9];
    const float* W15  = (const float*)d_in[10];
    const float* b15  = (const float*)d_in[11];

    const int E = in_sizes[1];
    const int n = in_sizes[0] / 256;   // NFEAT = 256
    float* out = (float*)d_out;

    float *z, *h, *sup, *accum;
    cudaGetSymbolAddress((void**)&z,     g_z);
    cudaGetSymbolAddress((void**)&h,     g_h);
    cudaGetSymbolAddress((void**)&sup,   g_sup);
    cudaGetSymbolAddress((void**)&accum, g_acc);

    const int TB = 256;
    const int gridE = (E + TB - 1) / TB;
    const int gridN = (n + TB - 1) / TB;
    const int gridGemm = (n + 63) / 64;
    const int gridSpmm = (n + 7) / 8;        // 8 warps/block
    const int gridAcc = (n + 31) / 32;

    // 1. CSR build
    zero_deg_kernel<<<gridN, TB>>>(n);
    hist_kernel<<<gridE, TB>>>(edst, E);
    scan_kernel<<<1, 1024>>>(n);
    scatter_kernel<<<gridE, TB>>>(esrc, edst, ew, E);

    // 2. layer 1: z = x@W0+b0 ; sup = x@W1 ; h = relu(agg(sup)+b1) + z
    gemm128_kernel<<<gridGemm, 256>>>(x, W0, b0, z, n, 256);
    gemm128_kernel<<<gridGemm, 256>>>(x, W1, nullptr, sup, n, 256);
    spmm_relu_res_kernel<<<gridSpmm, 256>>>(sup, b1, z, h, n);
    // x1 occupies W15 row block (14-1)*128 = 13*128
    acc_gemm40_kernel<<<gridAcc, dim3(40, 8)>>>(h, W15 + (size_t)13 * 128 * 40, accum, n, 1);

    // 3. mid layers l=0..12 produce x_{l+2}; W15 block offset (12-l)*128
    for (int l = 0; l < 13; l++) {
        gemm128_kernel<<<gridGemm, 256>>>(h, Wmid + (size_t)l * 128 * 128, nullptr, sup, n, 128);
        spmm_relu_res_kernel<<<gridSpmm, 256>>>(sup, bmid + (size_t)l * 128, h, h, n);
        acc_gemm40_kernel<<<gridAcc, dim3(40, 8)>>>(h, W15 + (size_t)(12 - l) * 128 * 40, accum, n, 0);
    }

    // 4. final: agg40 + b15 + log_softmax
    spmm40_lsm_kernel<<<gridSpmm, 256>>>(accum, b15, out, n);
}

// round 3
// speedup vs baseline: 1.5417x; 1.5417x over previous
#include <cuda_runtime.h>
#include <cuda_bf16.h>
#include <math.h>
#include <stdint.h>

// ---------------------------------------------------------------------------
// ResGCN15 on GB300 (sm_103 target -> no tcgen05; use mma.sync HMMA bf16).
// fp32 emulated as bf16 hi/lo split: a*b ~= ah*bh + ah*bl + al*bh (3 MMAs).
// Weights pre-split+transposed once; activations split in the SpMM epilogue.
// Final [N,1792]@[1792,40] done as ONE GEMM over the bf16 history buffer.
// ---------------------------------------------------------------------------

#define MAX_N 50000
#define MAX_E 800000
#define NHID 128
#define NCLASS 40
#define LDK 40          // smem row stride in bf16 elems (32 used + 8 pad = 80B)

// weight-transpose buffer offsets (element counts)
#define WOFF_W0   0
#define WOFF_W1   32768
#define WOFF_MID  65536
#define WOFF_W15  278528          // 65536 + 13*16384
#define WT_TOTAL  364544          // + 48*1792

__device__ __align__(16) int   g_deg[MAX_N];
__device__ __align__(16) int   g_offs[MAX_N + 1];
__device__ __align__(16) int   g_cursor[MAX_N];
__device__ __align__(16) int   g_csr_src[MAX_E];
__device__ __align__(16) float g_csr_w[MAX_E];
__device__ __align__(16) float g_z[(size_t)MAX_N * NHID];
__device__ __align__(16) float g_h[(size_t)MAX_N * NHID];
__device__ __align__(16) float g_sup[(size_t)MAX_N * NHID];
__device__ __align__(16) float g_acc[(size_t)MAX_N * NCLASS];
__device__ __align__(16) __nv_bfloat16 g_wthi[WT_TOTAL];
__device__ __align__(16) __nv_bfloat16 g_wtlo[WT_TOTAL];
__device__ __align__(16) __nv_bfloat16 g_xhi[(size_t)MAX_N * 256];
__device__ __align__(16) __nv_bfloat16 g_xlo[(size_t)MAX_N * 256];
__device__ __align__(16) __nv_bfloat16 g_hhi[(size_t)14 * MAX_N * NHID];
__device__ __align__(16) __nv_bfloat16 g_hlo[(size_t)14 * MAX_N * NHID];

// ---------------------------------------------------------------------------
// helpers
// ---------------------------------------------------------------------------
__device__ __forceinline__ uint32_t s2u(const void* p) {
    return (uint32_t)__cvta_generic_to_shared(p);
}
__device__ __forceinline__ void ldsm4(uint32_t* r, uint32_t addr) {
    asm volatile("ldmatrix.sync.aligned.m8n8.x4.shared.b16 {%0,%1,%2,%3}, [%4];"
                 : "=r"(r[0]), "=r"(r[1]), "=r"(r[2]), "=r"(r[3]) : "r"(addr));
}
__device__ __forceinline__ void mma_bf16(float* d, const uint32_t* a,
                                         uint32_t b0, uint32_t b1) {
    asm volatile(
        "mma.sync.aligned.m16n8k16.row.col.f32.bf16.bf16.f32 "
        "{%0,%1,%2,%3}, {%4,%5,%6,%7}, {%8,%9}, {%0,%1,%2,%3};"
        : "+f"(d[0]), "+f"(d[1]), "+f"(d[2]), "+f"(d[3])
        : "r"(a[0]), "r"(a[1]), "r"(a[2]), "r"(a[3]), "r"(b0), "r"(b1));
}
__device__ __forceinline__ void split1(float v, __nv_bfloat16& h, __nv_bfloat16& l) {
    h = __float2bfloat16(v);
    l = __float2bfloat16(v - __bfloat162float(h));
}

// ---------------------------------------------------------------------------
// CSR build
// ---------------------------------------------------------------------------
__global__ void zero_deg_kernel(int n) {
    int i = blockIdx.x * blockDim.x + threadIdx.x;
    if (i < n) g_deg[i] = 0;
}
__global__ void hist_kernel(const int* __restrict__ dst, int E) {
    int i = blockIdx.x * blockDim.x + threadIdx.x;
    if (i < E) atomicAdd(&g_deg[dst[i]], 1);
}
__global__ void scan_kernel(int n) {
    __shared__ int sums[1024];
    const int t = threadIdx.x;
    const int chunk = (n + 1023) >> 10;
    const int begin = t * chunk;
    const int end = min(begin + chunk, n);
    int s = 0;
    for (int i = begin; i < end; i++) s += g_deg[i];
    sums[t] = s;
    __syncthreads();
    for (int d = 1; d < 1024; d <<= 1) {
        int v = (t >= d) ? sums[t - d] : 0;
        __syncthreads();
        sums[t] += v;
        __syncthreads();
    }
    int run = (t == 0) ? 0 : sums[t - 1];
    if (t == 0) g_offs[0] = 0;
    for (int i = begin; i < end; i++) {
        g_cursor[i] = run;
        run += g_deg[i];
        g_offs[i + 1] = run;
    }
}
__global__ void scatter_kernel(const int* __restrict__ src, const int* __restrict__ dst,
                               const float* __restrict__ w, int E) {
    int i = blockIdx.x * blockDim.x + threadIdx.x;
    if (i < E) {
        int d = dst[i];
        int pos = atomicAdd(&g_cursor[d], 1);
        g_csr_src[pos] = src[i];
        g_csr_w[pos] = w[i];
    }
}

// ---------------------------------------------------------------------------
// prep: split weights (transposed to [n][k]) and x into bf16 hi/lo
// ---------------------------------------------------------------------------
__global__ void split_w_kernel(const float* __restrict__ W0, const float* __restrict__ W1,
                               const float* __restrict__ Wmid, const float* __restrict__ W15) {
    int i = blockIdx.x * blockDim.x + threadIdx.x;
    if (i >= WT_TOTAL) return;
    float v;
    if (i < 32768) {                       // W0t[n][k], n<128, k<256
        int n = i >> 8, k = i & 255;
        v = W0[k * 128 + n];
    } else if (i < 65536) {
        int j = i - 32768;
        int n = j >> 8, k = j & 255;
        v = W1[k * 128 + n];
    } else if (i < 278528) {               // Wmidt[l][n][k]
        int j = i - 65536;
        int l = j >> 14, jj = j & 16383;
        int n = jj >> 7, k = jj & 127;
        v = Wmid[l * 16384 + k * 128 + n];
    } else {                               // W15t[n][k], n<48 (pad rows 40..47 = 0)
        int j = i - 278528;
        int n = j / 1792, k = j % 1792;
        v = (n < 40) ? W15[(size_t)k * 40 + n] : 0.f;
    }
    __nv_bfloat16 h, l;
    split1(v, h, l);
    g_wthi[i] = h;
    g_wtlo[i] = l;
}
__global__ void split_x_kernel(const float* __restrict__ x, int total) {
    int i = blockIdx.x * blockDim.x + threadIdx.x;
    if (i >= total) return;
    __nv_bfloat16 h, l;
    split1(x[i], h, l);
    g_xhi[i] = h;
    g_xlo[i] = l;
}

// ---------------------------------------------------------------------------
// GEMM: C[M,128] = A[M,K] @ B[K,128] (+bias), via bf16 hi/lo mma.sync.
// A row-major split (Ahi/Alo, ld=K); B pre-transposed split Bt[n][k] (ld=K).
// Block: 128x128, 8 warps (4x2), warp tile 32x64. BK=32.
// ---------------------------------------------------------------------------
__global__ void __launch_bounds__(256) tgemm_kernel(
    const __nv_bfloat16* __restrict__ Ahi, const __nv_bfloat16* __restrict__ Alo,
    const __nv_bfloat16* __restrict__ Bhi, const __nv_bfloat16* __restrict__ Blo,
    const float* __restrict__ bias, float* __restrict__ C, int M, int K)
{
    __shared__ __align__(16) __nv_bfloat16 sAh[128 * LDK], sAl[128 * LDK];
    __shared__ __align__(16) __nv_bfloat16 sBh[128 * LDK], sBl[128 * LDK];
    const int tid = threadIdx.x, lane = tid & 31, wid = tid >> 5;
    const int row0 = blockIdx.x * 128;
    const int wm = wid & 3, wn = wid >> 2;

    float acc[2][8][4];
#pragma unroll
    for (int a = 0; a < 2; a++)
#pragma unroll
        for (int b = 0; b < 8; b++)
#pragma unroll
            for (int c = 0; c < 4; c++) acc[a][b][c] = 0.f;

    // ldmatrix lane offsets
    const int a_r = (lane & 7) + ((lane >> 3) & 1) * 8;
    const int a_c = (lane >> 4) * 8;
    const int b_r = (lane & 7) + (lane >> 4) * 8;
    const int b_c = ((lane >> 3) & 1) * 8;

    for (int k0 = 0; k0 < K; k0 += 32) {
#pragma unroll
        for (int i = tid; i < 512; i += 256) {
            int r = i >> 2, g = i & 3;
            uint4 vh = make_uint4(0, 0, 0, 0), vl = make_uint4(0, 0, 0, 0);
            if (row0 + r < M) {
                size_t go = (size_t)(row0 + r) * K + k0 + g * 8;
                vh = *(const uint4*)(Ahi + go);
                vl = *(const uint4*)(Alo + go);
            }
            *(uint4*)(sAh + r * LDK + g * 8) = vh;
            *(uint4*)(sAl + r * LDK + g * 8) = vl;
        }
#pragma unroll
        for (int i = tid; i < 512; i += 256) {
            int r = i >> 2, g = i & 3;
            size_t go = (size_t)r * K + k0 + g * 8;
            *(uint4*)(sBh + r * LDK + g * 8) = *(const uint4*)(Bhi + go);
            *(uint4*)(sBl + r * LDK + g * 8) = *(const uint4*)(Blo + go);
        }
        __syncthreads();
#pragma unroll
        for (int k16 = 0; k16 < 32; k16 += 16) {
            uint32_t ah[2][4], al[2][4];
#pragma unroll
            for (int mt = 0; mt < 2; mt++) {
                int er = wm * 32 + mt * 16 + a_r;
                int ec = k16 + a_c;
                ldsm4(ah[mt], s2u(sAh + er * LDK + ec));
                ldsm4(al[mt], s2u(sAl + er * LDK + ec));
            }
#pragma unroll
            for (int p = 0; p < 4; p++) {
                int er = wn * 64 + p * 16 + b_r;
                int ec = k16 + b_c;
                uint32_t bh[4], bl[4];
                ldsm4(bh, s2u(sBh + er * LDK + ec));
                ldsm4(bl, s2u(sBl + er * LDK + ec));
#pragma unroll
                for (int mt = 0; mt < 2; mt++) {
                    mma_bf16(acc[mt][2 * p],     ah[mt], bh[0], bh[1]);
                    mma_bf16(acc[mt][2 * p],     ah[mt], bl[0], bl[1]);
                    mma_bf16(acc[mt][2 * p],     al[mt], bh[0], bh[1]);
                    mma_bf16(acc[mt][2 * p + 1], ah[mt], bh[2], bh[3]);
                    mma_bf16(acc[mt][2 * p + 1], ah[mt], bl[2], bl[3]);
                    mma_bf16(acc[mt][2 * p + 1], al[mt], bh[2], bh[3]);
                }
            }
        }
        __syncthreads();
    }
    // epilogue
    const int er0 = row0 + wm * 32 + (lane >> 2);
    const int ec0 = wn * 64 + (lane & 3) * 2;
#pragma unroll
    for (int mt = 0; mt < 2; mt++) {
#pragma unroll
        for (int nt = 0; nt < 8; nt++) {
            int col = ec0 + nt * 8;
            float bx = 0.f, by = 0.f;
            if (bias) { bx = bias[col]; by = bias[col + 1]; }
            int r1 = er0 + mt * 16, r2 = r1 + 8;
            if (r1 < M) {
                float2 o = make_float2(acc[mt][nt][0] + bx, acc[mt][nt][1] + by);
                *(float2*)(C + (size_t)r1 * 128 + col) = o;
            }
            if (r2 < M) {
                float2 o = make_float2(acc[mt][nt][2] + bx, acc[mt][nt][3] + by);
                *(float2*)(C + (size_t)r2 * 128 + col) = o;
            }
        }
    }
}

// ---------------------------------------------------------------------------
// Final GEMM: C[M,40] = X_cat[M,1792] @ W15[1792,40].
// X_cat chunk c covers k = c*32..c*32+31; slab = 13 - (k>>7).
// 8 warps, each 16 rows x 48 cols (40 real). W15t padded to 48 rows.
// ---------------------------------------------------------------------------
__global__ void __launch_bounds__(256) tgemm40_kernel(
    const __nv_bfloat16* __restrict__ Hhi, const __nv_bfloat16* __restrict__ Hlo,
    const __nv_bfloat16* __restrict__ Bhi, const __nv_bfloat16* __restrict__ Blo,
    float* __restrict__ C, int M)
{
    __shared__ __align__(16) __nv_bfloat16 sAh[128 * LDK], sAl[128 * LDK];
    __shared__ __align__(16) __nv_bfloat16 sBh[48 * LDK], sBl[48 * LDK];
    const int tid = threadIdx.x, lane = tid & 31, wid = tid >> 5;
    const int row0 = blockIdx.x * 128;
    const size_t slabE = (size_t)M * 128;

    float acc[6][4];
#pragma unroll
    for (int a = 0; a < 6; a++)
#pragma unroll
        for (int c = 0; c < 4; c++) acc[a][c] = 0.f;

    const int a_r = (lane & 7) + ((lane >> 3) & 1) * 8;
    const int a_c = (lane >> 4) * 8;
    const int b_r = (lane & 7) + (lane >> 4) * 8;
    const int b_c = ((lane >> 3) & 1) * 8;

    for (int c = 0; c < 56; c++) {
        const int k0g = c * 32;
        const int slab = 13 - (k0g >> 7);
        const int kin = k0g & 127;
        const __nv_bfloat16* Ah = Hhi + (size_t)slab * slabE;
        const __nv_bfloat16* Al = Hlo + (size_t)slab * slabE;
#pragma unroll
        for (int i = tid; i < 512; i += 256) {
            int r = i >> 2, g = i & 3;
            uint4 vh = make_uint4(0, 0, 0, 0), vl = make_uint4(0, 0, 0, 0);
            if (row0 + r < M) {
                size_t go = (size_t)(row0 + r) * 128 + kin + g * 8;
                vh = *(const uint4*)(Ah + go);
                vl = *(const uint4*)(Al + go);
            }
            *(uint4*)(sAh + r * LDK + g * 8) = vh;
            *(uint4*)(sAl + r * LDK + g * 8) = vl;
        }
        if (tid < 192) {
            int r = tid >> 2, g = tid & 3;
            size_t go = (size_t)r * 1792 + k0g + g * 8;
            *(uint4*)(sBh + r * LDK + g * 8) = *(const uint4*)(Bhi + go);
            *(uint4*)(sBl + r * LDK + g * 8) = *(const uint4*)(Blo + go);
        }
        __syncthreads();
#pragma unroll
        for (int k16 = 0; k16 < 32; k16 += 16) {
            uint32_t ah[4], al[4];
            int er = wid * 16 + a_r;
            int ec = k16 + a_c;
            ldsm4(ah, s2u(sAh + er * LDK + ec));
            ldsm4(al, s2u(sAl + er * LDK + ec));
#pragma unroll
            for (int p = 0; p < 3; p++) {
                int br = p * 16 + b_r;
                int bc = k16 + b_c;
                uint32_t bh[4], bl[4];
                ldsm4(bh, s2u(sBh + br * LDK + bc));
                ldsm4(bl, s2u(sBl + br * LDK + bc));
                mma_bf16(acc[2 * p],     ah, bh[0], bh[1]);
                mma_bf16(acc[2 * p],     ah, bl[0], bl[1]);
                mma_bf16(acc[2 * p],     al, bh[0], bh[1]);
                mma_bf16(acc[2 * p + 1], ah, bh[2], bh[3]);
                mma_bf16(acc[2 * p + 1], ah, bl[2], bl[3]);
                mma_bf16(acc[2 * p + 1], al, bh[2], bh[3]);
            }
        }
        __syncthreads();
    }
    const int r1 = row0 + wid * 16 + (lane >> 2);
    const int r2 = r1 + 8;
#pragma unroll
    for (int nt = 0; nt < 5; nt++) {                 // cols 0..39 only
        int col = nt * 8 + (lane & 3) * 2;
        if (r1 < M) *(float2*)(C + (size_t)r1 * 40 + col) =
            make_float2(acc[nt][0], acc[nt][1]);
        if (r2 < M) *(float2*)(C + (size_t)r2 * 40 + col) =
            make_float2(acc[nt][2], acc[nt][3]);
    }
}

// ---------------------------------------------------------------------------
// SpMM d=128: warp per node. out = relu(agg + bias) + res (fp32),
// also writes bf16 hi/lo split of out into the history slab.
// ---------------------------------------------------------------------------
__global__ void __launch_bounds__(256) spmm_relu_res_kernel(
    const float* __restrict__ support, const float* __restrict__ bias,
    const float* __restrict__ res, float* __restrict__ out,
    __nv_bfloat16* __restrict__ outhi, __nv_bfloat16* __restrict__ outlo, int n)
{
    const int node = (blockIdx.x * blockDim.x + threadIdx.x) >> 5;
    if (node >= n) return;
    const int lane = threadIdx.x & 31;
    const int s = g_offs[node], e = g_offs[node + 1];
    const float4* sup4 = (const float4*)support;

    float4 acc = make_float4(0.f, 0.f, 0.f, 0.f);
    int i = s;
    for (; i + 1 < e; i += 2) {
        int s0 = g_csr_src[i], s1 = g_csr_src[i + 1];
        float w0 = g_csr_w[i],  w1 = g_csr_w[i + 1];
        float4 v0 = sup4[(size_t)s0 * 32 + lane];
        float4 v1 = sup4[(size_t)s1 * 32 + lane];
        acc.x = fmaf(w0, v0.x, acc.x); acc.y = fmaf(w0, v0.y, acc.y);
        acc.z = fmaf(w0, v0.z, acc.z); acc.w = fmaf(w0, v0.w, acc.w);
        acc.x = fmaf(w1, v1.x, acc.x); acc.y = fmaf(w1, v1.y, acc.y);
        acc.z = fmaf(w1, v1.z, acc.z); acc.w = fmaf(w1, v1.w, acc.w);
    }
    if (i < e) {
        int s0 = g_csr_src[i];
        float w0 = g_csr_w[i];
        float4 v0 = sup4[(size_t)s0 * 32 + lane];
        acc.x = fmaf(w0, v0.x, acc.x); acc.y = fmaf(w0, v0.y, acc.y);
        acc.z = fmaf(w0, v0.z, acc.z); acc.w = fmaf(w0, v0.w, acc.w);
    }
    float4 b = ((const float4*)bias)[lane];
    float4 r = ((const float4*)res)[(size_t)node * 32 + lane];
    float4 o;
    o.x = fmaxf(acc.x + b.x, 0.f) + r.x;
    o.y = fmaxf(acc.y + b.y, 0.f) + r.y;
    o.z = fmaxf(acc.z + b.z, 0.f) + r.z;
    o.w = fmaxf(acc.w + b.w, 0.f) + r.w;
    ((float4*)out)[(size_t)node * 32 + lane] = o;

    // bf16 hi/lo split for the GEMM path
    __nv_bfloat16 h0, l0, h1, l1, h2, l2, h3, l3;
    split1(o.x, h0, l0); split1(o.y, h1, l1);
    split1(o.z, h2, l2); split1(o.w, h3, l3);
    uint2 wh, wl;
    wh.x = (uint32_t)__bfloat16_as_ushort(h0) | ((uint32_t)__bfloat16_as_ushort(h1) << 16);
    wh.y = (uint32_t)__bfloat16_as_ushort(h2) | ((uint32_t)__bfloat16_as_ushort(h3) << 16);
    wl.x = (uint32_t)__bfloat16_as_ushort(l0) | ((uint32_t)__bfloat16_as_ushort(l1) << 16);
    wl.y = (uint32_t)__bfloat16_as_ushort(l2) | ((uint32_t)__bfloat16_as_ushort(l3) << 16);
    ((uint2*)(outhi + (size_t)node * 128))[lane] = wh;
    ((uint2*)(outlo + (size_t)node * 128))[lane] = wl;
}

// ---------------------------------------------------------------------------
// Final: agg40 + b15 + log_softmax. Warp per node.
// ---------------------------------------------------------------------------
__global__ void __launch_bounds__(256) spmm40_lsm_kernel(
    const float* __restrict__ accum, const float* __restrict__ b15,
    float* __restrict__ out, int n)
{
    const int node = (blockIdx.x * blockDim.x + threadIdx.x) >> 5;
    if (node >= n) return;
    const int lane = threadIdx.x & 31;
    const int s = g_offs[node], e = g_offs[node + 1];

    float a1 = 0.f, a2 = 0.f;
    for (int i = s; i < e; i++) {
        int src = g_csr_src[i];
        float w = g_csr_w[i];
        const float* row = accum + (size_t)src * 40;
        a1 = fmaf(w, row[lane], a1);
        if (lane < 8) a2 = fmaf(w, row[32 + lane], a2);
    }
    float v1 = a1 + b15[lane];
    float v2 = (lane < 8) ? (a2 + b15[32 + lane]) : -3.0e38f;

    float m = fmaxf(v1, v2);
#pragma unroll
    for (int o = 16; o > 0; o >>= 1) m = fmaxf(m, __shfl_xor_sync(0xffffffffu, m, o));
    float sum = expf(v1 - m) + ((lane < 8) ? expf(v2 - m) : 0.f);
#pragma unroll
    for (int o = 16; o > 0; o >>= 1) sum += __shfl_xor_sync(0xffffffffu, sum, o);
    float ls = m + logf(sum);

    out[(size_t)node * 40 + lane] = v1 - ls;
    if (lane < 8) out[(size_t)node * 40 + 32 + lane] = v2 - ls;
}

// ---------------------------------------------------------------------------
// Launch
// ---------------------------------------------------------------------------
extern "C" void kernel_launch(void* const* d_in, const int* in_sizes, int n_in,
                              void* d_out, int out_size)
{
    const float* x    = (const float*)d_in[0];
    const int*   esrc = (const int*)  d_in[1];
    const int*   edst = (const int*)  d_in[2];
    const float* ew   = (const float*)d_in[3];
    const float* W0   = (const float*)d_in[4];
    const float* b0   = (const float*)d_in[5];
    const float* W1   = (const float*)d_in[6];
    const float* b1   = (const float*)d_in[7];
    const float* Wmid = (const float*)d_in[8];
    const float* bmid = (const float*)d_in[9];
    const float* W15  = (const float*)d_in[10];
    const float* b15  = (const float*)d_in[11];

    const int E = in_sizes[1];
    const int n = in_sizes[0] / 256;   // NFEAT = 256
    float* out = (float*)d_out;

    float *z, *h, *sup, *accum;
    __nv_bfloat16 *wthi, *wtlo, *xhi, *xlo, *hhi, *hlo;
    cudaGetSymbolAddress((void**)&z,     g_z);
    cudaGetSymbolAddress((void**)&h,     g_h);
    cudaGetSymbolAddress((void**)&sup,   g_sup);
    cudaGetSymbolAddress((void**)&accum, g_acc);
    cudaGetSymbolAddress((void**)&wthi,  g_wthi);
    cudaGetSymbolAddress((void**)&wtlo,  g_wtlo);
    cudaGetSymbolAddress((void**)&xhi,   g_xhi);
    cudaGetSymbolAddress((void**)&xlo,   g_xlo);
    cudaGetSymbolAddress((void**)&hhi,   g_hhi);
    cudaGetSymbolAddress((void**)&hlo,   g_hlo);

    const int TB = 256;
    const int gridE = (E + TB - 1) / TB;
    const int gridN = (n + TB - 1) / TB;
    const int gridT = (n + 127) / 128;
    const int gridSpmm = (n + 7) / 8;
    const size_t slab = (size_t)n * 128;

    // 1. CSR build + splits
    zero_deg_kernel<<<gridN, TB>>>(n);
    hist_kernel<<<gridE, TB>>>(edst, E);
    scan_kernel<<<1, 1024>>>(n);
    scatter_kernel<<<gridE, TB>>>(esrc, edst, ew, E);
    split_w_kernel<<<(WT_TOTAL + TB - 1) / TB, TB>>>(W0, W1, Wmid, W15);
    split_x_kernel<<<(n * 256 + TB - 1) / TB, TB>>>(x, n * 256);

    // 2. layer 1
    tgemm_kernel<<<gridT, 256>>>(xhi, xlo, wthi + WOFF_W0, wtlo + WOFF_W0, b0, z, n, 256);
    tgemm_kernel<<<gridT, 256>>>(xhi, xlo, wthi + WOFF_W1, wtlo + WOFF_W1, nullptr, sup, n, 256);
    spmm_relu_res_kernel<<<gridSpmm, 256>>>(sup, b1, z, h, hhi, hlo, n);

    // 3. mid layers
    for (int l = 0; l < 13; l++) {
        tgemm_kernel<<<gridT, 256>>>(hhi + (size_t)l * slab, hlo + (size_t)l * slab,
                                     wthi + WOFF_MID + (size_t)l * 16384,
                                     wtlo + WOFF_MID + (size_t)l * 16384,
                                     nullptr, sup, n, 128);
        spmm_relu_res_kernel<<<gridSpmm, 256>>>(sup, bmid + (size_t)l * 128, h, h,
                                                hhi + (size_t)(l + 1) * slab,
                                                hlo + (size_t)(l + 1) * slab, n);
    }

    // 4. final concat GEMM
    tgemm40_kernel<<<gridT, 256>>>(hhi, hlo, wthi + WOFF_W15, wtlo + WOFF_W15, accum, n);

    // 5. agg40 + b15 + log_softmax
    spmm40_lsm_kernel<<<gridSpmm, 256>>>(accum, b15, out, n);
}